// round 5
// baseline (speedup 1.0000x reference)
#include <cuda_runtime.h>
#include <cuda_bf16.h>
#include <cstdint>

// ---------------------------------------------------------------------------
// TRIZRL: encoder(tanh) -> 40-expert batched GEMM(+bias,relu) -> softmax router
//         -> jax.random.categorical(threefry, partitionable) -> gather -> decoder
// Outputs concatenated in tuple order: out[B,5], probs[B,40], h[B,40,64]
// ---------------------------------------------------------------------------

#define MAXB 131072
#define NEXP 40
#define HID  64
#define NCOL (NEXP * HID)   // 2560

__device__ float g_z[(size_t)MAXB * HID];   // encoder activations (scratch)
__device__ int   g_idx[MAXB];               // sampled expert index

// ---------------- f32x2 helpers (Blackwell packed fp32) --------------------
__device__ __forceinline__ unsigned long long dupf2(float v) {
    unsigned long long r;
    asm("mov.b64 %0, {%1, %1};" : "=l"(r) : "f"(v));
    return r;
}
__device__ __forceinline__ unsigned long long fma_f32x2(unsigned long long a,
                                                        unsigned long long b,
                                                        unsigned long long c) {
    unsigned long long d;
    asm("fma.rn.f32x2 %0, %1, %2, %3;" : "=l"(d) : "l"(a), "l"(b), "l"(c));
    return d;
}
__device__ __forceinline__ float2 unpackf2(unsigned long long v) {
    float2 r;
    asm("mov.b64 {%0, %1}, %2;" : "=f"(r.x), "=f"(r.y) : "l"(v));
    return r;
}

// ---------------- Threefry-2x32-20, key = (0,1)  (jax.random.key(1)) -------
__device__ __forceinline__ uint2 threefry01(uint32_t x0, uint32_t x1) {
    const uint32_t ks0 = 0u, ks1 = 1u, ks2 = 0x1BD11BDBu;  // 0^1^0x1BD11BDA
    x0 += ks0; x1 += ks1;
#define TFR(r) { x0 += x1; x1 = (x1 << (r)) | (x1 >> (32 - (r))); x1 ^= x0; }
    TFR(13) TFR(15) TFR(26) TFR(6)   x0 += ks1; x1 += ks2 + 1u;
    TFR(17) TFR(29) TFR(16) TFR(24)  x0 += ks2; x1 += ks0 + 2u;
    TFR(13) TFR(15) TFR(26) TFR(6)   x0 += ks0; x1 += ks1 + 3u;
    TFR(17) TFR(29) TFR(16) TFR(24)  x0 += ks1; x1 += ks2 + 4u;
    TFR(13) TFR(15) TFR(26) TFR(6)   x0 += ks2; x1 += ks0 + 5u;
#undef TFR
    return make_uint2(x0, x1);
}

// jax partitionable threefry (default since jax 0.4.30):
//   per-element counter (hi32(i), lo32(i)); 32-bit draw = lane0 ^ lane1.
__device__ __forceinline__ float gumbel_sample(uint32_t flat_idx) {
    uint2 r = threefry01(0u, flat_idx);
    uint32_t bits = r.x ^ r.y;
    // jax _uniform: bitcast((bits>>9)|0x3f800000) - 1, into [tiny, 1)
    float f = __uint_as_float((bits >> 9) | 0x3f800000u) - 1.0f;
    const float TINY = 1.17549435e-38f;
    float u = fmaxf(f, TINY);
    return -logf(-logf(u));
}

// ---------------- Kernel 1: encoder z = tanh(x @ enc_w^T + enc_b) ----------
__global__ void enc_kernel(const float* __restrict__ x,
                           const float* __restrict__ ew,
                           const float* __restrict__ eb) {
    int t = blockIdx.x * blockDim.x + threadIdx.x;   // B*64 threads
    int b = t >> 6, j = t & 63;
    const float* xr = x + (size_t)b * 5;
    float a = __ldg(eb + j);
    #pragma unroll
    for (int d = 0; d < 5; ++d) a = fmaf(__ldg(xr + d), __ldg(ew + j * 5 + d), a);
    g_z[t] = tanhf(a);
}

// ---------------- Kernel 2: router softmax + categorical sampling ----------
// One warp per row. Lanes own experts {lane} and (lane<8) {lane+32}.
__global__ void policy_kernel(const float* __restrict__ pol_w,
                              const float* __restrict__ pol_b,
                              float* __restrict__ probs, int B) {
    __shared__ float sW[NEXP * 65];
    __shared__ float sB[NEXP];
    __shared__ float sZ[8][HID];
    int tid = threadIdx.x;
    for (int i = tid; i < NEXP * HID; i += 256)
        sW[(i / HID) * 65 + (i % HID)] = pol_w[i];
    if (tid < NEXP) sB[tid] = pol_b[tid];
    __syncthreads();

    int wid = tid >> 5, lane = tid & 31;
    int gw = blockIdx.x * 8 + wid;
    int warpsTotal = gridDim.x * 8;

    for (int b = gw; b < B; b += warpsTotal) {
        const float* zr = g_z + (size_t)b * HID;
        sZ[wid][lane]      = zr[lane];
        sZ[wid][lane + 32] = zr[lane + 32];
        __syncwarp();

        float acc1 = 0.f, acc2 = 0.f;
        #pragma unroll
        for (int d = 0; d < HID; ++d) {
            float zd = sZ[wid][d];
            acc1 = fmaf(zd, sW[lane * 65 + d], acc1);
            if (lane < 8) acc2 = fmaf(zd, sW[(lane + 32) * 65 + d], acc2);
        }
        float v1 = acc1 + sB[lane];
        float v2 = (lane < 8) ? (acc2 + sB[lane + 32]) : -INFINITY;

        float m = fmaxf(v1, v2);
        #pragma unroll
        for (int off = 16; off; off >>= 1) m = fmaxf(m, __shfl_xor_sync(~0u, m, off));
        float e1 = expf(v1 - m);
        float e2 = (lane < 8) ? expf(v2 - m) : 0.f;
        float s = e1 + e2;
        #pragma unroll
        for (int off = 16; off; off >>= 1) s += __shfl_xor_sync(~0u, s, off);
        float p1 = e1 / s;
        float p2 = e2 / s;
        probs[(size_t)b * NEXP + lane] = p1;
        if (lane < 8) probs[(size_t)b * NEXP + 32 + lane] = p2;

        // categorical: argmax(log(probs) + gumbel), partitionable threefry
        uint32_t base = (uint32_t)b * (uint32_t)NEXP;
        float val1 = logf(p1) + gumbel_sample(base + lane);
        float val2 = -INFINITY;
        if (lane < 8) val2 = logf(p2) + gumbel_sample(base + 32 + lane);

        float bv; int bk;
        if (val2 > val1) { bv = val2; bk = lane + 32; } else { bv = val1; bk = lane; }
        #pragma unroll
        for (int off = 16; off; off >>= 1) {
            float ov = __shfl_xor_sync(~0u, bv, off);
            int   ok = __shfl_xor_sync(~0u, bk, off);
            if (ov > bv || (ov == bv && ok < bk)) { bv = ov; bk = ok; }
        }
        if (lane == 0) g_idx[b] = bk;
        __syncwarp();
    }
}

// ---------------- Kernel 3: h = relu(z @ W^T + bias), W = triz_w [2560,64] --
// 128x128 tile, K=64 resident, f32x2 packed FMA (M-paired accumulators).
#define BM 128
#define BN 128
#define BK 64
#define AS_STRIDE (BM + 4)
#define BS_STRIDE (BN + 4)
#define SMEM_GEMM ((BK * AS_STRIDE + BK * BS_STRIDE) * 4)

__global__ void __launch_bounds__(256, 2)
gemm_h_kernel(const float* __restrict__ W, const float* __restrict__ bias,
              float* __restrict__ H) {
    extern __shared__ float sm[];
    float* As = sm;                       // [BK][AS_STRIDE], transposed (k-major)
    float* Bs = sm + BK * AS_STRIDE;      // [BK][BS_STRIDE]

    int tid = threadIdx.x;
    size_t bm = (size_t)blockIdx.y * BM;
    int bn = blockIdx.x * BN;

    const float* Z = g_z;
    #pragma unroll
    for (int it = 0; it < 8; ++it) {
        int i = tid + it * 256;               // (m, k4)
        int m = i >> 4, k4 = (i & 15) << 2;
        float4 v = *(const float4*)(Z + (bm + m) * HID + k4);
        As[(k4 + 0) * AS_STRIDE + m] = v.x;
        As[(k4 + 1) * AS_STRIDE + m] = v.y;
        As[(k4 + 2) * AS_STRIDE + m] = v.z;
        As[(k4 + 3) * AS_STRIDE + m] = v.w;
    }
    #pragma unroll
    for (int it = 0; it < 8; ++it) {
        int i = tid + it * 256;
        int n = i >> 4, k4 = (i & 15) << 2;
        float4 v = *(const float4*)(W + (size_t)(bn + n) * HID + k4);
        Bs[(k4 + 0) * BS_STRIDE + n] = v.x;
        Bs[(k4 + 1) * BS_STRIDE + n] = v.y;
        Bs[(k4 + 2) * BS_STRIDE + n] = v.z;
        Bs[(k4 + 3) * BS_STRIDE + n] = v.w;
    }
    __syncthreads();

    int tx = tid & 15, ty = tid >> 4;
    int m0 = ty * 8, n0 = tx * 8;

    unsigned long long acc[4][8];
    #pragma unroll
    for (int i = 0; i < 4; ++i)
        #pragma unroll
        for (int j = 0; j < 8; ++j) acc[i][j] = 0ull;

    #pragma unroll
    for (int k = 0; k < BK; ++k) {
        unsigned long long a2[4];
        #pragma unroll
        for (int i = 0; i < 4; ++i)
            a2[i] = *(const unsigned long long*)&As[k * AS_STRIDE + m0 + 2 * i];
        float4 bv0 = *(const float4*)&Bs[k * BS_STRIDE + n0];
        float4 bv1 = *(const float4*)&Bs[k * BS_STRIDE + n0 + 4];
        unsigned long long b2[8];
        b2[0] = dupf2(bv0.x); b2[1] = dupf2(bv0.y);
        b2[2] = dupf2(bv0.z); b2[3] = dupf2(bv0.w);
        b2[4] = dupf2(bv1.x); b2[5] = dupf2(bv1.y);
        b2[6] = dupf2(bv1.z); b2[7] = dupf2(bv1.w);
        #pragma unroll
        for (int i = 0; i < 4; ++i)
            #pragma unroll
            for (int j = 0; j < 8; ++j)
                acc[i][j] = fma_f32x2(a2[i], b2[j], acc[i][j]);
    }

    float bcol[8];
    *(float4*)&bcol[0] = *(const float4*)(bias + bn + n0);
    *(float4*)&bcol[4] = *(const float4*)(bias + bn + n0 + 4);

    #pragma unroll
    for (int i = 0; i < 4; ++i) {
        float r0[8], r1[8];
        #pragma unroll
        for (int j = 0; j < 8; ++j) {
            float2 p = unpackf2(acc[i][j]);
            r0[j] = fmaxf(p.x + bcol[j], 0.f);
            r1[j] = fmaxf(p.y + bcol[j], 0.f);
        }
        float* o0 = H + (bm + m0 + 2 * i) * (size_t)NCOL + bn + n0;
        float* o1 = o0 + NCOL;
        *(float4*)(o0)     = make_float4(r0[0], r0[1], r0[2], r0[3]);
        *(float4*)(o0 + 4) = make_float4(r0[4], r0[5], r0[6], r0[7]);
        *(float4*)(o1)     = make_float4(r1[0], r1[1], r1[2], r1[3]);
        *(float4*)(o1 + 4) = make_float4(r1[4], r1[5], r1[6], r1[7]);
    }
}

// ---------------- Kernel 4: decoder out = h[b, idx[b], :] @ dec_w^T + dec_b -
__global__ void dec_kernel(const float* __restrict__ H,
                           const float* __restrict__ dw,
                           const float* __restrict__ db,
                           float* __restrict__ out, int B) {
    __shared__ float sw[5 * HID];
    __shared__ float sb[5];
    int tid = threadIdx.x;
    for (int i = tid; i < 5 * HID; i += 256) sw[i] = dw[i];
    if (tid < 5) sb[tid] = db[tid];
    __syncthreads();

    int b = blockIdx.x * 256 + tid;
    if (b >= B) return;
    const float4* hr = (const float4*)(H + (size_t)b * NCOL + g_idx[b] * HID);
    float acc[5];
    #pragma unroll
    for (int j = 0; j < 5; ++j) acc[j] = sb[j];
    #pragma unroll
    for (int q = 0; q < 16; ++q) {
        float4 v = hr[q];
        #pragma unroll
        for (int j = 0; j < 5; ++j) {
            acc[j] = fmaf(v.x, sw[j * HID + q * 4 + 0], acc[j]);
            acc[j] = fmaf(v.y, sw[j * HID + q * 4 + 1], acc[j]);
            acc[j] = fmaf(v.z, sw[j * HID + q * 4 + 2], acc[j]);
            acc[j] = fmaf(v.w, sw[j * HID + q * 4 + 3], acc[j]);
        }
    }
    float* o = out + (size_t)b * 5;
    #pragma unroll
    for (int j = 0; j < 5; ++j) o[j] = acc[j];
}

// ---------------------------------------------------------------------------
extern "C" void kernel_launch(void* const* d_in, const int* in_sizes, int n_in,
                              void* d_out, int out_size) {
    const float* x      = (const float*)d_in[0];
    const float* enc_w  = (const float*)d_in[1];
    const float* enc_b  = (const float*)d_in[2];
    const float* triz_w = (const float*)d_in[3];   // [40,64,64] == W[2560,64]
    const float* triz_b = (const float*)d_in[4];   // [40,64]    == bias[2560]
    const float* pol_w  = (const float*)d_in[5];
    const float* pol_b  = (const float*)d_in[6];
    const float* dec_w  = (const float*)d_in[7];
    const float* dec_b  = (const float*)d_in[8];

    int B = in_sizes[0] / 5;

    float* out   = (float*)d_out;                  // [B,5]
    float* probs = out + (size_t)B * 5;            // [B,40]
    float* h     = probs + (size_t)B * NEXP;       // [B,40,64]

    enc_kernel<<<(B * HID) / 256, 256>>>(x, enc_w, enc_b);
    policy_kernel<<<1024, 256>>>(pol_w, pol_b, probs, B);

    cudaFuncSetAttribute(gemm_h_kernel,
                         cudaFuncAttributeMaxDynamicSharedMemorySize, SMEM_GEMM);
    dim3 grid(NCOL / BN, B / BM);
    gemm_h_kernel<<<grid, 256, SMEM_GEMM>>>(triz_w, triz_b, h);

    dec_kernel<<<(B + 255) / 256, 256>>>(h, dec_w, dec_b, out, B);
}

// round 7
// speedup vs baseline: 1.0698x; 1.0698x over previous
#include <cuda_runtime.h>
#include <cuda_bf16.h>
#include <cstdint>

// ---------------------------------------------------------------------------
// TRIZRL: encoder(tanh) -> 40-expert batched GEMM(+bias,relu) -> softmax router
//         -> jax.random.categorical(threefry, partitionable) -> gather -> decoder
// Outputs: out[B,5], probs[B,40], h[B,40,64]
// R6: tcgen05 unavailable (harness targets sm_103, not sm_103a). h-GEMM uses
//     mma.sync m16n8k16 bf16 (legacy HMMA) with split precision folded into a
//     single K=192 GEMM: A=[z1|z1|z2], B=[w1|w2|w1].
// ---------------------------------------------------------------------------

#define MAXB 131072
#define NEXP 40
#define HID  64
#define NCOL (NEXP * HID)   // 2560
#define KC   192            // concat K: z1w1 + z1w2 + z2w1
#define SPAD 200            // smem row stride in bf16 (400B -> conflict-free)

__device__ float         g_z [(size_t)MAXB * HID];  // fp32 z (policy)
__device__ __nv_bfloat16 g_zc[(size_t)MAXB * KC];   // A concat [z1|z1|z2]
__device__ __nv_bfloat16 g_wc[(size_t)NCOL * KC];   // B concat [w1|w2|w1]
__device__ int           g_idx[MAXB];

// ---------------- Threefry-2x32-20, key (0,1); partitionable path ----------
__device__ __forceinline__ uint2 threefry01(uint32_t x0, uint32_t x1) {
    const uint32_t ks0 = 0u, ks1 = 1u, ks2 = 0x1BD11BDBu;
    x0 += ks0; x1 += ks1;
#define TFR(r) { x0 += x1; x1 = (x1 << (r)) | (x1 >> (32 - (r))); x1 ^= x0; }
    TFR(13) TFR(15) TFR(26) TFR(6)   x0 += ks1; x1 += ks2 + 1u;
    TFR(17) TFR(29) TFR(16) TFR(24)  x0 += ks2; x1 += ks0 + 2u;
    TFR(13) TFR(15) TFR(26) TFR(6)   x0 += ks0; x1 += ks1 + 3u;
    TFR(17) TFR(29) TFR(16) TFR(24)  x0 += ks1; x1 += ks2 + 4u;
    TFR(13) TFR(15) TFR(26) TFR(6)   x0 += ks2; x1 += ks0 + 5u;
#undef TFR
    return make_uint2(x0, x1);
}
__device__ __forceinline__ float gumbel_sample(uint32_t flat_idx) {
    uint2 r = threefry01(0u, flat_idx);
    uint32_t bits = r.x ^ r.y;
    float f = __uint_as_float((bits >> 9) | 0x3f800000u) - 1.0f;
    float u = fmaxf(f, 1.17549435e-38f);
    return -logf(-logf(u));
}

// ---------------- Kernel 1: encoder (+ concat bf16 split emit) -------------
__global__ void enc_kernel(const float* __restrict__ x,
                           const float* __restrict__ ew,
                           const float* __restrict__ eb) {
    int t = blockIdx.x * blockDim.x + threadIdx.x;   // B*64 threads
    int b = t >> 6, j = t & 63;
    const float* xr = x + (size_t)b * 5;
    float a = __ldg(eb + j);
    #pragma unroll
    for (int d = 0; d < 5; ++d) a = fmaf(__ldg(xr + d), __ldg(ew + j * 5 + d), a);
    float z = tanhf(a);
    g_z[t] = z;
    __nv_bfloat16 hi = __float2bfloat16(z);
    __nv_bfloat16 lo = __float2bfloat16(z - __bfloat162float(hi));
    __nv_bfloat16* row = g_zc + (size_t)b * KC;
    row[j]       = hi;   // k 0..63   : z1
    row[j + 64]  = hi;   // k 64..127 : z1 (pairs with w2)
    row[j + 128] = lo;   // k 128..191: z2 (pairs with w1)
}

// ---------------- Kernel 1b: weight concat split ---------------------------
__global__ void wsplit_kernel(const float* __restrict__ w) {
    int i = blockIdx.x * 256 + threadIdx.x;     // NCOL*HID
    if (i >= NCOL * HID) return;
    int n = i >> 6, k = i & 63;
    float v = w[i];
    __nv_bfloat16 hi = __float2bfloat16(v);
    __nv_bfloat16 lo = __float2bfloat16(v - __bfloat162float(hi));
    __nv_bfloat16* row = g_wc + (size_t)n * KC;
    row[k]       = hi;   // w1
    row[k + 64]  = lo;   // w2 (pairs with z1)
    row[k + 128] = hi;   // w1 (pairs with z2)
}

// ---------------- Kernel 2: router softmax + categorical -------------------
__global__ void policy_kernel(const float* __restrict__ pol_w,
                              const float* __restrict__ pol_b,
                              float* __restrict__ probs, int B) {
    __shared__ float sW[NEXP * 65];
    __shared__ float sB[NEXP];
    __shared__ float sZ[8][HID];
    int tid = threadIdx.x;
    for (int i = tid; i < NEXP * HID; i += 256)
        sW[(i / HID) * 65 + (i % HID)] = pol_w[i];
    if (tid < NEXP) sB[tid] = pol_b[tid];
    __syncthreads();

    int wid = tid >> 5, lane = tid & 31;
    int gw = blockIdx.x * 8 + wid;
    int warpsTotal = gridDim.x * 8;

    for (int b = gw; b < B; b += warpsTotal) {
        const float* zr = g_z + (size_t)b * HID;
        sZ[wid][lane]      = zr[lane];
        sZ[wid][lane + 32] = zr[lane + 32];
        __syncwarp();

        float acc1 = 0.f, acc2 = 0.f;
        #pragma unroll
        for (int d = 0; d < HID; ++d) {
            float zd = sZ[wid][d];
            acc1 = fmaf(zd, sW[lane * 65 + d], acc1);
            if (lane < 8) acc2 = fmaf(zd, sW[(lane + 32) * 65 + d], acc2);
        }
        float v1 = acc1 + sB[lane];
        float v2 = (lane < 8) ? (acc2 + sB[lane + 32]) : -INFINITY;

        float m = fmaxf(v1, v2);
        #pragma unroll
        for (int off = 16; off; off >>= 1) m = fmaxf(m, __shfl_xor_sync(~0u, m, off));
        float e1 = expf(v1 - m);
        float e2 = (lane < 8) ? expf(v2 - m) : 0.f;
        float s = e1 + e2;
        #pragma unroll
        for (int off = 16; off; off >>= 1) s += __shfl_xor_sync(~0u, s, off);
        float p1 = e1 / s, p2 = e2 / s;
        probs[(size_t)b * NEXP + lane] = p1;
        if (lane < 8) probs[(size_t)b * NEXP + 32 + lane] = p2;

        uint32_t base = (uint32_t)b * (uint32_t)NEXP;
        float val1 = logf(p1) + gumbel_sample(base + lane);
        float val2 = -INFINITY;
        if (lane < 8) val2 = logf(p2) + gumbel_sample(base + 32 + lane);

        float bv; int bk;
        if (val2 > val1) { bv = val2; bk = lane + 32; } else { bv = val1; bk = lane; }
        #pragma unroll
        for (int off = 16; off; off >>= 1) {
            float ov = __shfl_xor_sync(~0u, bv, off);
            int   ok = __shfl_xor_sync(~0u, bk, off);
            if (ov > bv || (ov == bv && ok < bk)) { bv = ov; bk = ok; }
        }
        if (lane == 0) g_idx[b] = bk;
        __syncwarp();
    }
}

// ---------------- Kernel 3: h-GEMM via mma.sync bf16 (HMMA) ----------------
// CTA: M=128 rows, A tile resident in smem (128 x 192, stride 200).
// Loop 40 N-tiles of 64: B tile 64 x 192. 8 warps, warp tile m32 x n32.
// m16n8k16 fragments via direct LDS.32 (documented lane mapping).
__global__ void __launch_bounds__(256, 2)
gemm_h_mma(const float* __restrict__ bias, float* __restrict__ H) {
    extern __shared__ __nv_bfloat16 sm[];
    __nv_bfloat16* As = sm;               // [128][SPAD]
    __nv_bfloat16* Bs = sm + 128 * SPAD;  // [64][SPAD]

    int tid = threadIdx.x;
    size_t bm = (size_t)blockIdx.x * 128;

    // A tile: 128 rows x 192 bf16 = 3072 x 16B chunks
    #pragma unroll
    for (int it = 0; it < 12; ++it) {
        int i = tid + it * 256;
        int m = i / 24, c = i % 24;
        uint4 v = *(const uint4*)(g_zc + (bm + m) * KC + c * 8);
        *(uint4*)(As + m * SPAD + c * 8) = v;
    }

    int wid = tid >> 5, lane = tid & 31;
    int mw = (wid & 3) * 32;        // warp m offset
    int nw = (wid >> 2) * 32;       // warp n offset
    int lr = lane >> 2, lc = lane & 3;

    for (int t = 0; t < NEXP; ++t) {
        int bn = t * 64;
        // B tile: 64 x 192 = 1536 chunks
        #pragma unroll
        for (int it = 0; it < 6; ++it) {
            int i = tid + it * 256;
            int n = i / 24, c = i % 24;
            uint4 v = *(const uint4*)(g_wc + (size_t)(bn + n) * KC + c * 8);
            *(uint4*)(Bs + n * SPAD + c * 8) = v;
        }
        __syncthreads();

        float acc[2][4][4];
        #pragma unroll
        for (int f = 0; f < 2; ++f)
            #pragma unroll
            for (int g = 0; g < 4; ++g)
                #pragma unroll
                for (int e = 0; e < 4; ++e) acc[f][g][e] = 0.f;

        #pragma unroll
        for (int ks = 0; ks < KC / 16; ++ks) {
            int k0 = ks * 16 + lc * 2;
            uint32_t a[2][4], b[4][2];
            #pragma unroll
            for (int f = 0; f < 2; ++f) {
                const __nv_bfloat16* ap = As + (mw + f * 16 + lr) * SPAD + k0;
                a[f][0] = *(const uint32_t*)(ap);
                a[f][1] = *(const uint32_t*)(ap + 8 * SPAD);
                a[f][2] = *(const uint32_t*)(ap + 8);
                a[f][3] = *(const uint32_t*)(ap + 8 * SPAD + 8);
            }
            #pragma unroll
            for (int g = 0; g < 4; ++g) {
                const __nv_bfloat16* bp = Bs + (nw + g * 8 + lr) * SPAD + k0;
                b[g][0] = *(const uint32_t*)(bp);
                b[g][1] = *(const uint32_t*)(bp + 8);
            }
            #pragma unroll
            for (int f = 0; f < 2; ++f)
                #pragma unroll
                for (int g = 0; g < 4; ++g)
                    asm volatile(
                        "mma.sync.aligned.m16n8k16.row.col.f32.bf16.bf16.f32 "
                        "{%0,%1,%2,%3}, {%4,%5,%6,%7}, {%8,%9}, {%0,%1,%2,%3};"
                        : "+f"(acc[f][g][0]), "+f"(acc[f][g][1]),
                          "+f"(acc[f][g][2]), "+f"(acc[f][g][3])
                        : "r"(a[f][0]), "r"(a[f][1]), "r"(a[f][2]), "r"(a[f][3]),
                          "r"(b[g][0]), "r"(b[g][1]));
        }

        // bias + relu + store. c frag: rows lr, lr+8; cols 2*lc, 2*lc+1.
        #pragma unroll
        for (int g = 0; g < 4; ++g) {
            int col = bn + nw + g * 8 + lc * 2;
            float b0 = __ldg(bias + col), b1 = __ldg(bias + col + 1);
            #pragma unroll
            for (int f = 0; f < 2; ++f) {
                size_t r0 = bm + mw + f * 16 + lr;
                float2 v0 = make_float2(fmaxf(acc[f][g][0] + b0, 0.f),
                                        fmaxf(acc[f][g][1] + b1, 0.f));
                float2 v1 = make_float2(fmaxf(acc[f][g][2] + b0, 0.f),
                                        fmaxf(acc[f][g][3] + b1, 0.f));
                *(float2*)(H + r0 * NCOL + col)       = v0;
                *(float2*)(H + (r0 + 8) * NCOL + col) = v1;
            }
        }
        __syncthreads();   // protect Bs before next tile's overwrite
    }
}

// ---------------- Kernel 4: decoder ----------------------------------------
__global__ void dec_kernel(const float* __restrict__ H,
                           const float* __restrict__ dw,
                           const float* __restrict__ db,
                           float* __restrict__ out, int B) {
    __shared__ float sw[5 * HID];
    __shared__ float sb[5];
    int tid = threadIdx.x;
    for (int i = tid; i < 5 * HID; i += 256) sw[i] = dw[i];
    if (tid < 5) sb[tid] = db[tid];
    __syncthreads();

    int b = blockIdx.x * 256 + tid;
    if (b >= B) return;
    const float4* hr = (const float4*)(H + (size_t)b * NCOL + g_idx[b] * HID);
    float acc[5];
    #pragma unroll
    for (int j = 0; j < 5; ++j) acc[j] = sb[j];
    #pragma unroll
    for (int q = 0; q < 16; ++q) {
        float4 v = hr[q];
        #pragma unroll
        for (int j = 0; j < 5; ++j) {
            acc[j] = fmaf(v.x, sw[j * HID + q * 4 + 0], acc[j]);
            acc[j] = fmaf(v.y, sw[j * HID + q * 4 + 1], acc[j]);
            acc[j] = fmaf(v.z, sw[j * HID + q * 4 + 2], acc[j]);
            acc[j] = fmaf(v.w, sw[j * HID + q * 4 + 3], acc[j]);
        }
    }
    float* o = out + (size_t)b * 5;
    #pragma unroll
    for (int j = 0; j < 5; ++j) o[j] = acc[j];
}

// ---------------------------------------------------------------------------
#define SMEM_MMA ((128 * SPAD + 64 * SPAD) * 2)   // 76800 bytes

extern "C" void kernel_launch(void* const* d_in, const int* in_sizes, int n_in,
                              void* d_out, int out_size) {
    const float* x      = (const float*)d_in[0];
    const float* enc_w  = (const float*)d_in[1];
    const float* enc_b  = (const float*)d_in[2];
    const float* triz_w = (const float*)d_in[3];   // [40,64,64] == W[2560,64]
    const float* triz_b = (const float*)d_in[4];   // [40,64]    == bias[2560]
    const float* pol_w  = (const float*)d_in[5];
    const float* pol_b  = (const float*)d_in[6];
    const float* dec_w  = (const float*)d_in[7];
    const float* dec_b  = (const float*)d_in[8];

    int B = in_sizes[0] / 5;

    float* out   = (float*)d_out;                  // [B,5]
    float* probs = out + (size_t)B * 5;            // [B,40]
    float* h     = probs + (size_t)B * NEXP;       // [B,40,64]

    enc_kernel<<<(B * HID) / 256, 256>>>(x, enc_w, enc_b);
    wsplit_kernel<<<(NCOL * HID + 255) / 256, 256>>>(triz_w);
    policy_kernel<<<1024, 256>>>(pol_w, pol_b, probs, B);

    cudaFuncSetAttribute(gemm_h_mma,
                         cudaFuncAttributeMaxDynamicSharedMemorySize, SMEM_MMA);
    gemm_h_mma<<<B / 128, 256, SMEM_MMA>>>(triz_b, h);

    dec_kernel<<<(B + 255) / 256, 256>>>(h, dec_w, dec_b, out, B);
}

// round 9
// speedup vs baseline: 1.7780x; 1.6620x over previous
#include <cuda_runtime.h>
#include <cuda_bf16.h>
#include <cstdint>

// ---------------------------------------------------------------------------
// TRIZRL: encoder(tanh) -> 40-expert batched GEMM(+bias,relu) -> softmax router
//         -> jax.random.categorical(threefry, partitionable) -> gather -> decoder
// Outputs: out[B,5], probs[B,40], h[B,40,64]
// R8: GEMM fragments via ldmatrix.x4 (conflict-free) + register-prefetched B.
// ---------------------------------------------------------------------------

#define MAXB 131072
#define NEXP 40
#define HID  64
#define NCOL (NEXP * HID)   // 2560
#define KC   192            // concat K: z1w1 + z1w2 + z2w1
#define SPAD 200            // smem row stride in bf16 (400B, 16B-aligned, conflict-free)

__device__ float         g_z [(size_t)MAXB * HID];  // fp32 z (policy)
__device__ __nv_bfloat16 g_zc[(size_t)MAXB * KC];   // A concat [z1|z1|z2]
__device__ __nv_bfloat16 g_wc[(size_t)NCOL * KC];   // B concat [w1|w2|w1]
__device__ int           g_idx[MAXB];

// ---------------- Threefry-2x32-20, key (0,1); partitionable path ----------
__device__ __forceinline__ uint2 threefry01(uint32_t x0, uint32_t x1) {
    const uint32_t ks0 = 0u, ks1 = 1u, ks2 = 0x1BD11BDBu;
    x0 += ks0; x1 += ks1;
#define TFR(r) { x0 += x1; x1 = (x1 << (r)) | (x1 >> (32 - (r))); x1 ^= x0; }
    TFR(13) TFR(15) TFR(26) TFR(6)   x0 += ks1; x1 += ks2 + 1u;
    TFR(17) TFR(29) TFR(16) TFR(24)  x0 += ks2; x1 += ks0 + 2u;
    TFR(13) TFR(15) TFR(26) TFR(6)   x0 += ks0; x1 += ks1 + 3u;
    TFR(17) TFR(29) TFR(16) TFR(24)  x0 += ks1; x1 += ks2 + 4u;
    TFR(13) TFR(15) TFR(26) TFR(6)   x0 += ks2; x1 += ks0 + 5u;
#undef TFR
    return make_uint2(x0, x1);
}
__device__ __forceinline__ float gumbel_sample(uint32_t flat_idx) {
    uint2 r = threefry01(0u, flat_idx);
    uint32_t bits = r.x ^ r.y;
    float f = __uint_as_float((bits >> 9) | 0x3f800000u) - 1.0f;
    float u = fmaxf(f, 1.17549435e-38f);
    return -logf(-logf(u));
}

// ---------------- Kernel 1: encoder (+ concat bf16 split emit) -------------
__global__ void enc_kernel(const float* __restrict__ x,
                           const float* __restrict__ ew,
                           const float* __restrict__ eb) {
    int t = blockIdx.x * blockDim.x + threadIdx.x;   // B*64 threads
    int b = t >> 6, j = t & 63;
    const float* xr = x + (size_t)b * 5;
    float a = __ldg(eb + j);
    #pragma unroll
    for (int d = 0; d < 5; ++d) a = fmaf(__ldg(xr + d), __ldg(ew + j * 5 + d), a);
    float z = tanhf(a);
    g_z[t] = z;
    __nv_bfloat16 hi = __float2bfloat16(z);
    __nv_bfloat16 lo = __float2bfloat16(z - __bfloat162float(hi));
    __nv_bfloat16* row = g_zc + (size_t)b * KC;
    row[j]       = hi;   // k 0..63   : z1
    row[j + 64]  = hi;   // k 64..127 : z1 (pairs with w2)
    row[j + 128] = lo;   // k 128..191: z2 (pairs with w1)
}

// ---------------- Kernel 1b: weight concat split ---------------------------
__global__ void wsplit_kernel(const float* __restrict__ w) {
    int i = blockIdx.x * 256 + threadIdx.x;     // NCOL*HID
    if (i >= NCOL * HID) return;
    int n = i >> 6, k = i & 63;
    float v = w[i];
    __nv_bfloat16 hi = __float2bfloat16(v);
    __nv_bfloat16 lo = __float2bfloat16(v - __bfloat162float(hi));
    __nv_bfloat16* row = g_wc + (size_t)n * KC;
    row[k]       = hi;   // w1
    row[k + 64]  = lo;   // w2 (pairs with z1)
    row[k + 128] = hi;   // w1 (pairs with z2)
}

// ---------------- Kernel 2: router softmax + categorical -------------------
__global__ void policy_kernel(const float* __restrict__ pol_w,
                              const float* __restrict__ pol_b,
                              float* __restrict__ probs, int B) {
    __shared__ float sW[NEXP * 65];
    __shared__ float sB[NEXP];
    __shared__ float sZ[8][HID];
    int tid = threadIdx.x;
    for (int i = tid; i < NEXP * HID; i += 256)
        sW[(i / HID) * 65 + (i % HID)] = pol_w[i];
    if (tid < NEXP) sB[tid] = pol_b[tid];
    __syncthreads();

    int wid = tid >> 5, lane = tid & 31;
    int gw = blockIdx.x * 8 + wid;
    int warpsTotal = gridDim.x * 8;

    for (int b = gw; b < B; b += warpsTotal) {
        const float* zr = g_z + (size_t)b * HID;
        sZ[wid][lane]      = zr[lane];
        sZ[wid][lane + 32] = zr[lane + 32];
        __syncwarp();

        float acc1 = 0.f, acc2 = 0.f;
        #pragma unroll
        for (int d = 0; d < HID; ++d) {
            float zd = sZ[wid][d];
            acc1 = fmaf(zd, sW[lane * 65 + d], acc1);
            if (lane < 8) acc2 = fmaf(zd, sW[(lane + 32) * 65 + d], acc2);
        }
        float v1 = acc1 + sB[lane];
        float v2 = (lane < 8) ? (acc2 + sB[lane + 32]) : -INFINITY;

        float m = fmaxf(v1, v2);
        #pragma unroll
        for (int off = 16; off; off >>= 1) m = fmaxf(m, __shfl_xor_sync(~0u, m, off));
        float e1 = expf(v1 - m);
        float e2 = (lane < 8) ? expf(v2 - m) : 0.f;
        float s = e1 + e2;
        #pragma unroll
        for (int off = 16; off; off >>= 1) s += __shfl_xor_sync(~0u, s, off);
        float p1 = e1 / s, p2 = e2 / s;
        probs[(size_t)b * NEXP + lane] = p1;
        if (lane < 8) probs[(size_t)b * NEXP + 32 + lane] = p2;

        uint32_t base = (uint32_t)b * (uint32_t)NEXP;
        float val1 = logf(p1) + gumbel_sample(base + lane);
        float val2 = -INFINITY;
        if (lane < 8) val2 = logf(p2) + gumbel_sample(base + 32 + lane);

        float bv; int bk;
        if (val2 > val1) { bv = val2; bk = lane + 32; } else { bv = val1; bk = lane; }
        #pragma unroll
        for (int off = 16; off; off >>= 1) {
            float ov = __shfl_xor_sync(~0u, bv, off);
            int   ok = __shfl_xor_sync(~0u, bk, off);
            if (ov > bv || (ov == bv && ok < bk)) { bv = ov; bk = ok; }
        }
        if (lane == 0) g_idx[b] = bk;
        __syncwarp();
    }
}

// ---------------- Kernel 3: h-GEMM, ldmatrix + mma.sync bf16 ----------------
// CTA: M=128 rows resident (A smem 128x192, stride 200), 40 N-tiles of 64.
// 8 warps 4m x 2n, warp tile m32 x n32. B prefetched to regs (next tile).
__device__ __forceinline__ uint32_t smem_u32(const void* p) {
    uint32_t a;
    asm("{ .reg .u64 t; cvta.to.shared.u64 t, %1; cvt.u32.u64 %0, t; }" : "=r"(a) : "l"(p));
    return a;
}
#define LDMX4(r0, r1, r2, r3, addr) \
    asm volatile("ldmatrix.sync.aligned.m8n8.x4.shared.b16 {%0,%1,%2,%3}, [%4];" \
        : "=r"(r0), "=r"(r1), "=r"(r2), "=r"(r3) : "r"(addr))

__global__ void __launch_bounds__(256, 2)
gemm_h_mma(const float* __restrict__ bias, float* __restrict__ H) {
    extern __shared__ __nv_bfloat16 sm[];
    __nv_bfloat16* As = sm;               // [128][SPAD]
    __nv_bfloat16* Bs = sm + 128 * SPAD;  // [64][SPAD]

    int tid = threadIdx.x;
    size_t bm = (size_t)blockIdx.x * 128;

    // A tile: 128 rows x 192 bf16 = 3072 x 16B chunks (coalesced LDG.128)
    #pragma unroll
    for (int it = 0; it < 12; ++it) {
        int i = tid + it * 256;
        int m = i / 24, c = i % 24;
        uint4 v = *(const uint4*)(g_zc + (bm + m) * KC + c * 8);
        *(uint4*)(As + m * SPAD + c * 8) = v;
    }

    int wid = tid >> 5, lane = tid & 31;
    int mw = (wid & 3) * 32;        // warp m offset
    int nw = (wid >> 2) * 32;       // warp n offset
    int lr = lane >> 2, lc = lane & 3;

    uint32_t sbA = smem_u32(As), sbB = smem_u32(Bs);
    // ldmatrix per-lane byte offsets (x4 matrix id i = lane>>3):
    // A: row = (l&7) + (i&1)*8, khalf = i>>1
    uint32_t aoff = sbA + (((lane & 7) + ((lane >> 3) & 1) * 8) * 400
                           + ((lane >> 4) & 1) * 16);
    // B: row(n) = (l&7) + (i>>1)*8, khalf = i&1
    uint32_t boff = sbB + nw * 400 + (((lane & 7) + ((lane >> 4) & 1) * 8) * 400
                           + ((lane >> 3) & 1) * 16);

    // prefetch first B tile into regs
    uint4 pf[6];
    #pragma unroll
    for (int it = 0; it < 6; ++it) {
        int i = tid + it * 256;
        int n = i / 24, c = i % 24;
        pf[it] = *(const uint4*)(g_wc + (size_t)n * KC + c * 8);
    }

    for (int t = 0; t < NEXP; ++t) {
        int bn = t * 64;
        __syncthreads();                       // A ready / Bs fully consumed
        #pragma unroll
        for (int it = 0; it < 6; ++it) {
            int i = tid + it * 256;
            int n = i / 24, c = i % 24;
            *(uint4*)(Bs + n * SPAD + c * 8) = pf[it];
        }
        __syncthreads();                       // Bs ready

        // issue prefetch of next tile (consumed at next iteration's store)
        if (t + 1 < NEXP) {
            #pragma unroll
            for (int it = 0; it < 6; ++it) {
                int i = tid + it * 256;
                int n = i / 24, c = i % 24;
                pf[it] = *(const uint4*)(g_wc + (size_t)(bn + 64 + n) * KC + c * 8);
            }
        }

        float acc[2][4][4];
        #pragma unroll
        for (int f = 0; f < 2; ++f)
            #pragma unroll
            for (int g = 0; g < 4; ++g)
                #pragma unroll
                for (int e = 0; e < 4; ++e) acc[f][g][e] = 0.f;

        #pragma unroll
        for (int ks = 0; ks < KC / 16; ++ks) {
            uint32_t a[2][4], b[4][2];
            #pragma unroll
            for (int f = 0; f < 2; ++f)
                LDMX4(a[f][0], a[f][1], a[f][2], a[f][3],
                      aoff + (mw + f * 16) * 400 + ks * 32);
            LDMX4(b[0][0], b[0][1], b[1][0], b[1][1], boff + ks * 32);
            LDMX4(b[2][0], b[2][1], b[3][0], b[3][1], boff + ks * 32 + 6400);
            #pragma unroll
            for (int f = 0; f < 2; ++f)
                #pragma unroll
                for (int g = 0; g < 4; ++g)
                    asm volatile(
                        "mma.sync.aligned.m16n8k16.row.col.f32.bf16.bf16.f32 "
                        "{%0,%1,%2,%3}, {%4,%5,%6,%7}, {%8,%9}, {%0,%1,%2,%3};"
                        : "+f"(acc[f][g][0]), "+f"(acc[f][g][1]),
                          "+f"(acc[f][g][2]), "+f"(acc[f][g][3])
                        : "r"(a[f][0]), "r"(a[f][1]), "r"(a[f][2]), "r"(a[f][3]),
                          "r"(b[g][0]), "r"(b[g][1]));
        }

        // bias + relu + store. c frag: rows lr, lr+8; cols 2*lc, 2*lc+1.
        #pragma unroll
        for (int g = 0; g < 4; ++g) {
            int col = bn + nw + g * 8 + lc * 2;
            float b0 = __ldg(bias + col), b1 = __ldg(bias + col + 1);
            #pragma unroll
            for (int f = 0; f < 2; ++f) {
                size_t r0 = bm + mw + f * 16 + lr;
                float2 v0 = make_float2(fmaxf(acc[f][g][0] + b0, 0.f),
                                        fmaxf(acc[f][g][1] + b1, 0.f));
                float2 v1 = make_float2(fmaxf(acc[f][g][2] + b0, 0.f),
                                        fmaxf(acc[f][g][3] + b1, 0.f));
                *(float2*)(H + r0 * NCOL + col)       = v0;
                *(float2*)(H + (r0 + 8) * NCOL + col) = v1;
            }
        }
    }
}

// ---------------- Kernel 4: decoder ----------------------------------------
__global__ void dec_kernel(const float* __restrict__ H,
                           const float* __restrict__ dw,
                           const float* __restrict__ db,
                           float* __restrict__ out, int B) {
    __shared__ float sw[5 * HID];
    __shared__ float sb[5];
    int tid = threadIdx.x;
    for (int i = tid; i < 5 * HID; i += 256) sw[i] = dw[i];
    if (tid < 5) sb[tid] = db[tid];
    __syncthreads();

    int b = blockIdx.x * 256 + tid;
    if (b >= B) return;
    const float4* hr = (const float4*)(H + (size_t)b * NCOL + g_idx[b] * HID);
    float acc[5];
    #pragma unroll
    for (int j = 0; j < 5; ++j) acc[j] = sb[j];
    #pragma unroll
    for (int q = 0; q < 16; ++q) {
        float4 v = hr[q];
        #pragma unroll
        for (int j = 0; j < 5; ++j) {
            acc[j] = fmaf(v.x, sw[j * HID + q * 4 + 0], acc[j]);
            acc[j] = fmaf(v.y, sw[j * HID + q * 4 + 1], acc[j]);
            acc[j] = fmaf(v.z, sw[j * HID + q * 4 + 2], acc[j]);
            acc[j] = fmaf(v.w, sw[j * HID + q * 4 + 3], acc[j]);
        }
    }
    float* o = out + (size_t)b * 5;
    #pragma unroll
    for (int j = 0; j < 5; ++j) o[j] = acc[j];
}

// ---------------------------------------------------------------------------
#define SMEM_MMA ((128 * SPAD + 64 * SPAD) * 2)   // 76800 bytes

extern "C" void kernel_launch(void* const* d_in, const int* in_sizes, int n_in,
                              void* d_out, int out_size) {
    const float* x      = (const float*)d_in[0];
    const float* enc_w  = (const float*)d_in[1];
    const float* enc_b  = (const float*)d_in[2];
    const float* triz_w = (const float*)d_in[3];   // [40,64,64] == W[2560,64]
    const float* triz_b = (const float*)d_in[4];   // [40,64]    == bias[2560]
    const float* pol_w  = (const float*)d_in[5];
    const float* pol_b  = (const float*)d_in[6];
    const float* dec_w  = (const float*)d_in[7];
    const float* dec_b  = (const float*)d_in[8];

    int B = in_sizes[0] / 5;

    float* out   = (float*)d_out;                  // [B,5]
    float* probs = out + (size_t)B * 5;            // [B,40]
    float* h     = probs + (size_t)B * NEXP;       // [B,40,64]

    enc_kernel<<<(B * HID) / 256, 256>>>(x, enc_w, enc_b);
    wsplit_kernel<<<(NCOL * HID + 255) / 256, 256>>>(triz_w);
    policy_kernel<<<1024, 256>>>(pol_w, pol_b, probs, B);

    cudaFuncSetAttribute(gemm_h_mma,
                         cudaFuncAttributeMaxDynamicSharedMemorySize, SMEM_MMA);
    gemm_h_mma<<<B / 128, 256, SMEM_MMA>>>(triz_b, h);

    dec_kernel<<<(B + 255) / 256, 256>>>(h, dec_w, dec_b, out, B);
}

// round 13
// speedup vs baseline: 1.7998x; 1.0123x over previous
#include <cuda_runtime.h>
#include <cuda_bf16.h>
#include <cstdint>

// ---------------------------------------------------------------------------
// TRIZRL: encoder(tanh) -> 40-expert batched GEMM(+bias,relu) -> softmax router
//         -> jax.random.categorical(threefry, partitionable) -> gather -> decoder
// Outputs: out[B,5], probs[B,40], h[B,40,64]
// R12: fix R10's B-tile copy overrun (24 -> 12 iterations).
// ---------------------------------------------------------------------------

#define MAXB 131072
#define NEXP 40
#define HID  64
#define NCOL (NEXP * HID)   // 2560
#define KC   192            // concat K: z1w1 + z1w2 + z2w1
#define SPAD 200            // smem row stride in bf16 (400B)

__device__ float         g_z [(size_t)MAXB * HID];  // fp32 z (policy)
__device__ __nv_bfloat16 g_zc[(size_t)MAXB * KC];   // A concat [z1|z1|z2]
__device__ __nv_bfloat16 g_wc[(size_t)NCOL * KC];   // B concat [w1|w2|w1]
__device__ int           g_idx[MAXB];

// ---------------- Threefry-2x32-20, key (0,1); partitionable path ----------
__device__ __forceinline__ uint2 threefry01(uint32_t x0, uint32_t x1) {
    const uint32_t ks0 = 0u, ks1 = 1u, ks2 = 0x1BD11BDBu;
    x0 += ks0; x1 += ks1;
#define TFR(r) { x0 += x1; x1 = (x1 << (r)) | (x1 >> (32 - (r))); x1 ^= x0; }
    TFR(13) TFR(15) TFR(26) TFR(6)   x0 += ks1; x1 += ks2 + 1u;
    TFR(17) TFR(29) TFR(16) TFR(24)  x0 += ks2; x1 += ks0 + 2u;
    TFR(13) TFR(15) TFR(26) TFR(6)   x0 += ks0; x1 += ks1 + 3u;
    TFR(17) TFR(29) TFR(16) TFR(24)  x0 += ks1; x1 += ks2 + 4u;
    TFR(13) TFR(15) TFR(26) TFR(6)   x0 += ks2; x1 += ks0 + 5u;
#undef TFR
    return make_uint2(x0, x1);
}
__device__ __forceinline__ float gumbel_sample(uint32_t flat_idx) {
    uint2 r = threefry01(0u, flat_idx);
    uint32_t bits = r.x ^ r.y;
    float f = __uint_as_float((bits >> 9) | 0x3f800000u) - 1.0f;
    float u = fmaxf(f, 1.17549435e-38f);
    return -logf(-logf(u));
}

// ---------------- Kernel 1: encoder (+ concat bf16 split emit) -------------
__global__ void enc_kernel(const float* __restrict__ x,
                           const float* __restrict__ ew,
                           const float* __restrict__ eb) {
    int t = blockIdx.x * blockDim.x + threadIdx.x;   // B*64 threads
    int b = t >> 6, j = t & 63;
    const float* xr = x + (size_t)b * 5;
    float a = __ldg(eb + j);
    #pragma unroll
    for (int d = 0; d < 5; ++d) a = fmaf(__ldg(xr + d), __ldg(ew + j * 5 + d), a);
    float z = tanhf(a);
    g_z[t] = z;
    __nv_bfloat16 hi = __float2bfloat16(z);
    __nv_bfloat16 lo = __float2bfloat16(z - __bfloat162float(hi));
    __nv_bfloat16* row = g_zc + (size_t)b * KC;
    row[j]       = hi;   // k 0..63   : z1
    row[j + 64]  = hi;   // k 64..127 : z1 (pairs with w2)
    row[j + 128] = lo;   // k 128..191: z2 (pairs with w1)
}

// ---------------- Kernel 1b: weight concat split ---------------------------
__global__ void wsplit_kernel(const float* __restrict__ w) {
    int i = blockIdx.x * 256 + threadIdx.x;     // NCOL*HID
    if (i >= NCOL * HID) return;
    int n = i >> 6, k = i & 63;
    float v = w[i];
    __nv_bfloat16 hi = __float2bfloat16(v);
    __nv_bfloat16 lo = __float2bfloat16(v - __bfloat162float(hi));
    __nv_bfloat16* row = g_wc + (size_t)n * KC;
    row[k]       = hi;   // w1
    row[k + 64]  = lo;   // w2 (pairs with z1)
    row[k + 128] = hi;   // w1 (pairs with z2)
}

// ---------------- Kernel 2: router softmax + categorical -------------------
__global__ void policy_kernel(const float* __restrict__ pol_w,
                              const float* __restrict__ pol_b,
                              float* __restrict__ probs, int B) {
    __shared__ float sW[NEXP * 65];
    __shared__ float sB[NEXP];
    __shared__ float sZ[8][HID];
    int tid = threadIdx.x;
    for (int i = tid; i < NEXP * HID; i += 256)
        sW[(i / HID) * 65 + (i % HID)] = pol_w[i];
    if (tid < NEXP) sB[tid] = pol_b[tid];
    __syncthreads();

    int wid = tid >> 5, lane = tid & 31;
    int gw = blockIdx.x * 8 + wid;
    int warpsTotal = gridDim.x * 8;

    for (int b = gw; b < B; b += warpsTotal) {
        const float* zr = g_z + (size_t)b * HID;
        sZ[wid][lane]      = zr[lane];
        sZ[wid][lane + 32] = zr[lane + 32];
        __syncwarp();

        float acc1 = 0.f, acc2 = 0.f;
        #pragma unroll
        for (int d = 0; d < HID; ++d) {
            float zd = sZ[wid][d];
            acc1 = fmaf(zd, sW[lane * 65 + d], acc1);
            if (lane < 8) acc2 = fmaf(zd, sW[(lane + 32) * 65 + d], acc2);
        }
        float v1 = acc1 + sB[lane];
        float v2 = (lane < 8) ? (acc2 + sB[lane + 32]) : -INFINITY;

        float m = fmaxf(v1, v2);
        #pragma unroll
        for (int off = 16; off; off >>= 1) m = fmaxf(m, __shfl_xor_sync(~0u, m, off));
        float e1 = expf(v1 - m);
        float e2 = (lane < 8) ? expf(v2 - m) : 0.f;
        float s = e1 + e2;
        #pragma unroll
        for (int off = 16; off; off >>= 1) s += __shfl_xor_sync(~0u, s, off);
        float p1 = e1 / s, p2 = e2 / s;
        probs[(size_t)b * NEXP + lane] = p1;
        if (lane < 8) probs[(size_t)b * NEXP + 32 + lane] = p2;

        uint32_t base = (uint32_t)b * (uint32_t)NEXP;
        float val1 = logf(p1) + gumbel_sample(base + lane);
        float val2 = -INFINITY;
        if (lane < 8) val2 = logf(p2) + gumbel_sample(base + 32 + lane);

        float bv; int bk;
        if (val2 > val1) { bv = val2; bk = lane + 32; } else { bv = val1; bk = lane; }
        #pragma unroll
        for (int off = 16; off; off >>= 1) {
            float ov = __shfl_xor_sync(~0u, bv, off);
            int   ok = __shfl_xor_sync(~0u, bk, off);
            if (ov > bv || (ov == bv && ok < bk)) { bv = ov; bk = ok; }
        }
        if (lane == 0) g_idx[b] = bk;
        __syncwarp();
    }
}

// ---------------- Kernel 3: h-GEMM, ldmatrix + mma.sync bf16 ----------------
__device__ __forceinline__ uint32_t smem_u32(const void* p) {
    uint32_t a;
    asm("{ .reg .u64 t; cvta.to.shared.u64 t, %1; cvt.u32.u64 %0, t; }" : "=r"(a) : "l"(p));
    return a;
}
#define LDMX4(r0, r1, r2, r3, addr) \
    asm volatile("ldmatrix.sync.aligned.m8n8.x4.shared.b16 {%0,%1,%2,%3}, [%4];" \
        : "=r"(r0), "=r"(r1), "=r"(r2), "=r"(r3) : "r"(addr))

// 4x4 transpose of float2 elements within a quad (2 shfl_xor stages).
__device__ __forceinline__ void quad_tr4(unsigned long long* P, int lc) {
    {
        bool hi = lc & 2;
        unsigned long long s0 = hi ? P[0] : P[2];
        unsigned long long s1 = hi ? P[1] : P[3];
        unsigned long long r0 = __shfl_xor_sync(0xffffffffu, s0, 2);
        unsigned long long r1 = __shfl_xor_sync(0xffffffffu, s1, 2);
        if (hi) { P[0] = r0; P[1] = r1; } else { P[2] = r0; P[3] = r1; }
    }
    {
        bool od = lc & 1;
        unsigned long long s0 = od ? P[0] : P[1];
        unsigned long long s1 = od ? P[2] : P[3];
        unsigned long long r0 = __shfl_xor_sync(0xffffffffu, s0, 1);
        unsigned long long r1 = __shfl_xor_sync(0xffffffffu, s1, 1);
        if (od) { P[0] = r0; P[2] = r1; } else { P[1] = r0; P[3] = r1; }
    }
}
__device__ __forceinline__ unsigned long long pack2(float x, float y) {
    unsigned long long r;
    asm("mov.b64 %0, {%1, %2};" : "=l"(r) : "f"(x), "f"(y));
    return r;
}
__device__ __forceinline__ float2 unpack2(unsigned long long v) {
    float2 r;
    asm("mov.b64 {%0, %1}, %2;" : "=f"(r.x), "=f"(r.y) : "l"(v));
    return r;
}

// CTA: M=128 rows resident, 20 iterations of N=128 (2 expert tiles).
// 8 warps 4m x 2n, warp tile m32 x n64.
__global__ void __launch_bounds__(256, 2)
gemm_h_mma(const float* __restrict__ bias, float* __restrict__ H) {
    extern __shared__ __nv_bfloat16 sm[];
    __nv_bfloat16* As = sm;               // [128][SPAD]
    __nv_bfloat16* Bs = sm + 128 * SPAD;  // [128][SPAD]

    int tid = threadIdx.x;
    size_t bm = (size_t)blockIdx.x * 128;

    // A tile: 128 rows x 192 bf16 = 3072 x 16B chunks (coalesced LDG.128)
    #pragma unroll
    for (int it = 0; it < 12; ++it) {
        int i = tid + it * 256;
        int m = i / 24, c = i % 24;
        uint4 v = *(const uint4*)(g_zc + (bm + m) * KC + c * 8);
        *(uint4*)(As + m * SPAD + c * 8) = v;
    }

    int wid = tid >> 5, lane = tid & 31;
    int mw = (wid & 3) * 32;        // warp m offset
    int nw = (wid >> 2) * 64;       // warp n offset (n64 per warp)
    int lr = lane >> 2, lc = lane & 3;

    uint32_t sbA = smem_u32(As), sbB = smem_u32(Bs);
    uint32_t aoff = sbA + (((lane & 7) + ((lane >> 3) & 1) * 8) * 400
                           + ((lane >> 4) & 1) * 16);
    uint32_t boff = sbB + nw * 400 + (((lane & 7) + ((lane >> 4) & 1) * 8) * 400
                           + ((lane >> 3) & 1) * 16);

    for (int t = 0; t < NEXP / 2; ++t) {
        int bn = t * 128;
        __syncthreads();                   // prev Bs fully consumed
        // B tile: 128 rows x 192 bf16 = 3072 chunks of 16B (12 iterations!)
        #pragma unroll
        for (int it = 0; it < 12; ++it) {
            int i = tid + it * 256;
            int n = i / 24, c = i % 24;
            uint4 v = *(const uint4*)(g_wc + (size_t)(bn + n) * KC + c * 8);
            *(uint4*)(Bs + n * SPAD + c * 8) = v;
        }
        __syncthreads();                   // Bs ready

        float acc[2][8][4];
        #pragma unroll
        for (int f = 0; f < 2; ++f)
            #pragma unroll
            for (int g = 0; g < 8; ++g)
                #pragma unroll
                for (int e = 0; e < 4; ++e) acc[f][g][e] = 0.f;

        #pragma unroll
        for (int ks = 0; ks < KC / 16; ++ks) {
            uint32_t a[2][4], b[8][2];
            #pragma unroll
            for (int f = 0; f < 2; ++f)
                LDMX4(a[f][0], a[f][1], a[f][2], a[f][3],
                      aoff + (mw + f * 16) * 400 + ks * 32);
            #pragma unroll
            for (int gp = 0; gp < 4; ++gp)
                LDMX4(b[gp * 2][0], b[gp * 2][1], b[gp * 2 + 1][0], b[gp * 2 + 1][1],
                      boff + ks * 32 + gp * 6400);
            #pragma unroll
            for (int f = 0; f < 2; ++f)
                #pragma unroll
                for (int g = 0; g < 8; ++g)
                    asm volatile(
                        "mma.sync.aligned.m16n8k16.row.col.f32.bf16.bf16.f32 "
                        "{%0,%1,%2,%3}, {%4,%5,%6,%7}, {%8,%9}, {%0,%1,%2,%3};"
                        : "+f"(acc[f][g][0]), "+f"(acc[f][g][1]),
                          "+f"(acc[f][g][2]), "+f"(acc[f][g][3])
                        : "r"(a[f][0]), "r"(a[f][1]), "r"(a[f][2]), "r"(a[f][3]),
                          "r"(b[g][0]), "r"(b[g][1]));
        }

        // Epilogue: bias+relu, quad transpose, coalesced STG.128.
        #pragma unroll
        for (int f = 0; f < 2; ++f) {
            #pragma unroll
            for (int nh = 0; nh < 2; ++nh) {
                unsigned long long P[4], Q[4];
                #pragma unroll
                for (int g = 0; g < 4; ++g) {
                    int gg = nh * 4 + g;
                    int col = bn + nw + nh * 32 + g * 8 + lc * 2;
                    float b0 = __ldg(bias + col), b1 = __ldg(bias + col + 1);
                    P[g] = pack2(fmaxf(acc[f][gg][0] + b0, 0.f),
                                 fmaxf(acc[f][gg][1] + b1, 0.f));
                    Q[g] = pack2(fmaxf(acc[f][gg][2] + b0, 0.f),
                                 fmaxf(acc[f][gg][3] + b1, 0.f));
                }
                quad_tr4(P, lc);
                quad_tr4(Q, lc);
                // lane now owns cols [8*lc, 8*lc+8) of its row
                size_t r0 = bm + mw + f * 16 + lr;
                float* o0 = H + r0 * NCOL + bn + nw + nh * 32 + lc * 8;
                float* o1 = o0 + (size_t)8 * NCOL;
                float2 p0 = unpack2(P[0]), p1 = unpack2(P[1]);
                float2 p2 = unpack2(P[2]), p3 = unpack2(P[3]);
                float2 q0 = unpack2(Q[0]), q1 = unpack2(Q[1]);
                float2 q2 = unpack2(Q[2]), q3 = unpack2(Q[3]);
                *(float4*)(o0)     = make_float4(p0.x, p0.y, p1.x, p1.y);
                *(float4*)(o0 + 4) = make_float4(p2.x, p2.y, p3.x, p3.y);
                *(float4*)(o1)     = make_float4(q0.x, q0.y, q1.x, q1.y);
                *(float4*)(o1 + 4) = make_float4(q2.x, q2.y, q3.x, q3.y);
            }
        }
    }
}

// ---------------- Kernel 4: decoder ----------------------------------------
__global__ void dec_kernel(const float* __restrict__ H,
                           const float* __restrict__ dw,
                           const float* __restrict__ db,
                           float* __restrict__ out, int B) {
    __shared__ float sw[5 * HID];
    __shared__ float sb[5];
    int tid = threadIdx.x;
    for (int i = tid; i < 5 * HID; i += 256) sw[i] = dw[i];
    if (tid < 5) sb[tid] = db[tid];
    __syncthreads();

    int b = blockIdx.x * 256 + tid;
    if (b >= B) return;
    const float4* hr = (const float4*)(H + (size_t)b * NCOL + g_idx[b] * HID);
    float acc[5];
    #pragma unroll
    for (int j = 0; j < 5; ++j) acc[j] = sb[j];
    #pragma unroll
    for (int q = 0; q < 16; ++q) {
        float4 v = hr[q];
        #pragma unroll
        for (int j = 0; j < 5; ++j) {
            acc[j] = fmaf(v.x, sw[j * HID + q * 4 + 0], acc[j]);
            acc[j] = fmaf(v.y, sw[j * HID + q * 4 + 1], acc[j]);
            acc[j] = fmaf(v.z, sw[j * HID + q * 4 + 2], acc[j]);
            acc[j] = fmaf(v.w, sw[j * HID + q * 4 + 3], acc[j]);
        }
    }
    float* o = out + (size_t)b * 5;
    #pragma unroll
    for (int j = 0; j < 5; ++j) o[j] = acc[j];
}

// ---------------------------------------------------------------------------
#define SMEM_MMA ((128 * SPAD + 128 * SPAD) * 2)   // 102400 bytes

extern "C" void kernel_launch(void* const* d_in, const int* in_sizes, int n_in,
                              void* d_out, int out_size) {
    const float* x      = (const float*)d_in[0];
    const float* enc_w  = (const float*)d_in[1];
    const float* enc_b  = (const float*)d_in[2];
    const float* triz_w = (const float*)d_in[3];   // [40,64,64] == W[2560,64]
    const float* triz_b = (const float*)d_in[4];   // [40,64]    == bias[2560]
    const float* pol_w  = (const float*)d_in[5];
    const float* pol_b  = (const float*)d_in[6];
    const float* dec_w  = (const float*)d_in[7];
    const float* dec_b  = (const float*)d_in[8];

    int B = in_sizes[0] / 5;

    float* out   = (float*)d_out;                  // [B,5]
    float* probs = out + (size_t)B * 5;            // [B,40]
    float* h     = probs + (size_t)B * NEXP;       // [B,40,64]

    enc_kernel<<<(B * HID) / 256, 256>>>(x, enc_w, enc_b);
    wsplit_kernel<<<(NCOL * HID + 255) / 256, 256>>>(triz_w);
    policy_kernel<<<1024, 256>>>(pol_w, pol_b, probs, B);

    cudaFuncSetAttribute(gemm_h_mma,
                         cudaFuncAttributeMaxDynamicSharedMemorySize, SMEM_MMA);
    gemm_h_mma<<<B / 128, 256, SMEM_MMA>>>(triz_b, h);

    dec_kernel<<<(B + 255) / 256, 256>>>(h, dec_w, dec_b, out, B);
}